// round 14
// baseline (speedup 1.0000x reference)
#include <cuda_runtime.h>
#include <cuda_fp16.h>
#include <cstdint>

// Problem: B=8, C=256, H=W=32 -> N=1024, heads=8, dk=dv=32.

// ---------------- helpers ----------------
__device__ __forceinline__ uint32_t smem_u32(const void* p) {
    uint32_t a;
    asm("{ .reg .u64 t; cvta.to.shared.u64 t, %1; cvt.u32.u64 %0, t; }" : "=r"(a) : "l"(p));
    return a;
}
__device__ __forceinline__ void ldm_x4(uint32_t r[4], uint32_t addr) {
    asm volatile("ldmatrix.sync.aligned.m8n8.x4.shared.b16 {%0,%1,%2,%3}, [%4];"
                 : "=r"(r[0]), "=r"(r[1]), "=r"(r[2]), "=r"(r[3]) : "r"(addr));
}
__device__ __forceinline__ void ldm_x4t(uint32_t r[4], uint32_t addr) {
    asm volatile("ldmatrix.sync.aligned.m8n8.x4.trans.shared.b16 {%0,%1,%2,%3}, [%4];"
                 : "=r"(r[0]), "=r"(r[1]), "=r"(r[2]), "=r"(r[3]) : "r"(addr));
}
__device__ __forceinline__ void mma_f16(float* c, const uint32_t* a, const uint32_t* b) {
    asm volatile(
        "mma.sync.aligned.m16n8k16.row.col.f32.f16.f16.f32 "
        "{%0,%1,%2,%3}, {%4,%5,%6,%7}, {%8,%9}, {%0,%1,%2,%3};"
        : "+f"(c[0]), "+f"(c[1]), "+f"(c[2]), "+f"(c[3])
        : "r"(a[0]), "r"(a[1]), "r"(a[2]), "r"(a[3]), "r"(b[0]), "r"(b[1]));
}
__device__ __forceinline__ uint32_t pack_h2(float x, float y) {
    __half2 p = __float22half2_rn(make_float2(x, y));
    return *(uint32_t*)&p;
}
__device__ __forceinline__ uint32_t ex2_h2(uint32_t x) {
    uint32_t y; asm("ex2.approx.f16x2 %0, %1;" : "=r"(y) : "r"(x)); return y;
}
__device__ __forceinline__ void cp16(uint32_t dst, const void* src) {
    asm volatile("cp.async.cg.shared.global [%0], [%1], 16;" :: "r"(dst), "l"(src));
}
#define CP_COMMIT() asm volatile("cp.async.commit_group;" ::: "memory")
#define CP_WAIT0()  asm volatile("cp.async.wait_group 0;" ::: "memory")

// ---------------- scratch ----------------
__device__ __half g_wh[4 * 65536], g_wl[4 * 65536];   // Wq,Wk,Wv,Wo [m][k] hi/lo
__device__ __half g_xt[8*1024*256];                   // [b, n, c] pure fp16
__device__ __half g_q [8*8*1024*32];                  // [b,h,n,d] pure (scaled)
__device__ __half g_k [8*8*1024*32];                  // [b,h,n,d] pure
__device__ __half g_v [8*8*1024*32];                  // [b,h,n,d] pure
__device__ __half g_o [8*1024*256];                   // [b,n,cv] pure

// ---------------------------------------------------------------------------
// Fused prep: blocks 0..2047 transpose x -> xT fp16; 2048..3071 split weights.
// ---------------------------------------------------------------------------
__global__ void __launch_bounds__(256) prep_all(
    const float* __restrict__ x,
    const float* __restrict__ Wq, const float* __restrict__ Wk,
    const float* __restrict__ Wv, const float* __restrict__ Wo)
{
    __shared__ float tile[32][33];
    const int blk = blockIdx.x;
    const int tid = threadIdx.x;
    if (blk < 2048) {
        const int nblk = blk & 31, cblk = (blk >> 5) & 7, b = blk >> 8;
        const int n0 = nblk * 32, c0 = cblk * 32;
        const int tx = tid & 31, ty = tid >> 5;
#pragma unroll
        for (int i = 0; i < 4; i++)
            tile[ty + 8 * i][tx] = x[((size_t)b * 256 + c0 + ty + 8 * i) * 1024 + n0 + tx];
        __syncthreads();
#pragma unroll
        for (int i = 0; i < 4; i++)
            g_xt[((size_t)b * 1024 + n0 + ty + 8 * i) * 256 + c0 + tx] =
                __float2half_rn(tile[tx][ty + 8 * i]);
    } else {
        int idx = (blk - 2048) * 256 + tid;     // 0..262143
        int sel = idx >> 16, off = idx & 65535;
        const float* W = sel == 0 ? Wq : (sel == 1 ? Wk : (sel == 2 ? Wv : Wo));
        float v = W[off];
        __half h = __float2half_rn(v);
        g_wh[idx] = h;
        g_wl[idx] = __float2half_rn(v - __half2float(h));
    }
}

// ---------------------------------------------------------------------------
// GEMM core: acc += W[(MI*32)m x 256k] * X[128n x 256k]^T, TERMS in {1,2}.
// K-chunks of 64 (pitch-144), double-buffered; B-fragments prefetched 1 ks
// ahead to cover ldmatrix->MMA latency.
// ---------------------------------------------------------------------------
#define LDR 144
#define GEMM_SMEM 73728

template<int TERMS, int MI>
__device__ __forceinline__ void gemm_stage(
    const __half* __restrict__ Ah, const __half* __restrict__ Al,
    const __half* __restrict__ Bx,
    int mBase, int nBase, uint32_t sb, int tid, int kc, int s)
{
    constexpr uint32_t A_BYTES = (uint32_t)MI * 32 * LDR;
    constexpr uint32_t B_OFF   = A_BYTES * TERMS;
    constexpr uint32_t STAGE   = B_OFF + 128 * LDR;
    constexpr int A_ROWS = MI * 32;
    constexpr int ITERS = (A_ROWS * TERMS + 128) / 32;

    uint32_t base = sb + (uint32_t)s * STAGE;
#pragma unroll
    for (int i = 0; i < ITERS; i++) {
        int idx = tid + i * 256;
        int r = idx >> 3, part = idx & 7;
        uint32_t cOff = (uint32_t)part * 16;
        if (r < A_ROWS) {
            cp16(base + (uint32_t)r * LDR + cOff,
                 Ah + (size_t)(mBase + r) * 256 + kc * 64 + part * 8);
        } else if (TERMS == 2 && r < 2 * A_ROWS) {
            int rr = r - A_ROWS;
            cp16(base + A_BYTES + (uint32_t)rr * LDR + cOff,
                 Al + (size_t)(mBase + rr) * 256 + kc * 64 + part * 8);
        } else {
            int rr = r - A_ROWS * TERMS;
            cp16(base + B_OFF + (uint32_t)rr * LDR + cOff,
                 Bx + (size_t)(nBase + rr) * 256 + kc * 64 + part * 8);
        }
    }
}

template<int TERMS, int MI>
__device__ __forceinline__ void gemm_run(
    const __half* __restrict__ Ah, const __half* __restrict__ Al,
    const __half* __restrict__ Bx,
    int mBase, int nBase, uint32_t sb,
    int warpM, int warpN, int lane, int tid, float acc[MI][4][4])
{
    constexpr uint32_t A_BYTES = (uint32_t)MI * 32 * LDR;
    constexpr uint32_t AL_OFF  = A_BYTES;
    constexpr uint32_t B_OFF   = A_BYTES * TERMS;
    constexpr uint32_t STAGE   = B_OFF + 128 * LDR;

    const uint32_t aRow = (uint32_t)(lane & 15);
    const uint32_t aCol = (uint32_t)((lane >> 4) & 1) * 16;
    const uint32_t bRow = (uint32_t)((lane & 7) + ((lane >> 4) & 1) * 8);
    const uint32_t bCol = (uint32_t)((lane >> 3) & 1) * 16;
    const uint32_t bRowA = (uint32_t)(warpN * 32) + bRow;

    gemm_stage<TERMS, MI>(Ah, Al, Bx, mBase, nBase, sb, tid, 0, 0);
    CP_COMMIT(); CP_WAIT0(); __syncthreads();

    for (int kc = 0; kc < 4; kc++) {
        if (kc < 3) {
            gemm_stage<TERMS, MI>(Ah, Al, Bx, mBase, nBase, sb, tid, kc + 1, (kc + 1) & 1);
            CP_COMMIT();
        }
        const uint32_t kb = sb + (uint32_t)(kc & 1) * STAGE;

        uint32_t bf[2][2][4];   // double-buffered B fragments
#pragma unroll
        for (int nj = 0; nj < 2; nj++)
            ldm_x4(bf[0][nj], kb + B_OFF + (bRowA + nj * 16) * LDR + bCol);

#pragma unroll
        for (int ks = 0; ks < 4; ks++) {
            const uint32_t kOff = (uint32_t)ks * 32;
            const int cur = ks & 1, nxt = cur ^ 1;
            if (ks < 3) {
#pragma unroll
                for (int nj = 0; nj < 2; nj++)
                    ldm_x4(bf[nxt][nj],
                           kb + B_OFF + (bRowA + nj * 16) * LDR + (kOff + 32) + bCol);
            }
            uint32_t af[MI][4];
#pragma unroll
            for (int mi = 0; mi < MI; mi++) {
                uint32_t row = (uint32_t)(warpM * MI * 16 + mi * 16) + aRow;
                ldm_x4(af[mi], kb + row * LDR + kOff + aCol);
            }
#pragma unroll
            for (int mi = 0; mi < MI; mi++)
#pragma unroll
                for (int nj = 0; nj < 2; nj++) {
                    mma_f16(acc[mi][2 * nj + 0], af[mi], &bf[cur][nj][0]);
                    mma_f16(acc[mi][2 * nj + 1], af[mi], &bf[cur][nj][2]);
                }
            if (TERMS == 2) {
#pragma unroll
                for (int mi = 0; mi < MI; mi++) {
                    uint32_t row = (uint32_t)(warpM * MI * 16 + mi * 16) + aRow;
                    ldm_x4(af[mi], kb + AL_OFF + row * LDR + kOff + aCol);
                }
#pragma unroll
                for (int mi = 0; mi < MI; mi++)
#pragma unroll
                    for (int nj = 0; nj < 2; nj++) {
                        mma_f16(acc[mi][2 * nj + 0], af[mi], &bf[cur][nj][0]);
                        mma_f16(acc[mi][2 * nj + 1], af[mi], &bf[cur][nj][2]);
                    }
            }
        }
        if (kc < 3) { CP_WAIT0(); __syncthreads(); }
    }
}

// ---------------------------------------------------------------------------
// QKV projection: 64m x 128n tiles, grid (8,4,24). Q/K 2-term, V 1-term.
// ---------------------------------------------------------------------------
__global__ void __launch_bounds__(256, 2) qkv_gemm(
    const float* __restrict__ bq, const float* __restrict__ bk,
    const float* __restrict__ bv)
{
    extern __shared__ char smc[];
    const uint32_t sb = smem_u32(smc);
    const int tid = threadIdx.x, lane = tid & 31, wid = tid >> 5;
    const int z = blockIdx.z, b = z / 3, sel = z - 3 * b;
    const int mBase = blockIdx.y * 64;
    const int nBase = blockIdx.x * 128;
    const int warpM = wid >> 2, warpN = wid & 3;

    const float* bias = sel == 0 ? bq : (sel == 1 ? bk : bv);
    const float scale = sel == 0 ? 0.17677669529663687f * 1.4426950408889634f : 1.0f;
    __half* Yp = sel == 0 ? g_q : (sel == 1 ? g_k : g_v);

    float acc[2][4][4];
#pragma unroll
    for (int i = 0; i < 2; i++)
#pragma unroll
        for (int j = 0; j < 4; j++)
#pragma unroll
            for (int r = 0; r < 4; r++) acc[i][j][r] = 0.f;

    const __half* Xb = g_xt + (size_t)b * 1024 * 256;
    if (sel == 2)
        gemm_run<1, 2>(g_wh + 2 * 65536, nullptr, Xb,
                       mBase, nBase, sb, warpM, warpN, lane, tid, acc);
    else
        gemm_run<2, 2>(g_wh + sel * 65536, g_wl + sel * 65536, Xb,
                       mBase, nBase, sb, warpM, warpN, lane, tid, acc);

    const int g = lane >> 2, t4 = lane & 3;
#pragma unroll
    for (int mi = 0; mi < 2; mi++) {
        int m0 = mBase + warpM * 32 + mi * 16 + g;
        float bi0 = bias[m0], bi1 = bias[m0 + 8];
#pragma unroll
        for (int n8 = 0; n8 < 4; n8++) {
            int n = nBase + warpN * 32 + n8 * 8 + t4 * 2;
#pragma unroll
            for (int half = 0; half < 2; half++) {
                int mm = half ? m0 + 8 : m0;
                float bi = half ? bi1 : bi0;
                float v0 = (acc[mi][n8][2 * half + 0] + bi) * scale;
                float v1 = (acc[mi][n8][2 * half + 1] + bi) * scale;
                size_t base = (((size_t)b * 8 + (mm >> 5)) * 1024 + n) * 32 + (mm & 31);
                Yp[base] = __float2half_rn(v0);
                Yp[base + 32] = __float2half_rn(v1);
            }
        }
    }
}

// ---------------------------------------------------------------------------
// Output projection: 64m x 128n tiles, grid (8,4,8). 2-term. fp32 out [b,c,n].
// ---------------------------------------------------------------------------
__global__ void __launch_bounds__(256, 2) out_gemm(
    const float* __restrict__ bo, float* __restrict__ Y)
{
    extern __shared__ char smc[];
    const uint32_t sb = smem_u32(smc);
    const int tid = threadIdx.x, lane = tid & 31, wid = tid >> 5;
    const int b = blockIdx.z;
    const int mBase = blockIdx.y * 64;
    const int nBase = blockIdx.x * 128;
    const int warpM = wid >> 2, warpN = wid & 3;

    float acc[2][4][4];
#pragma unroll
    for (int i = 0; i < 2; i++)
#pragma unroll
        for (int j = 0; j < 4; j++)
#pragma unroll
            for (int r = 0; r < 4; r++) acc[i][j][r] = 0.f;

    gemm_run<2, 2>(g_wh + 3 * 65536, g_wl + 3 * 65536,
                   g_o + (size_t)b * 1024 * 256,
                   mBase, nBase, sb, warpM, warpN, lane, tid, acc);

    const int g = lane >> 2, t4 = lane & 3;
#pragma unroll
    for (int mi = 0; mi < 2; mi++) {
        int m0 = mBase + warpM * 32 + mi * 16 + g;
        float bi0 = bo[m0], bi1 = bo[m0 + 8];
#pragma unroll
        for (int n8 = 0; n8 < 4; n8++) {
            int n = nBase + warpN * 32 + n8 * 8 + t4 * 2;
#pragma unroll
            for (int half = 0; half < 2; half++) {
                int mm = half ? m0 + 8 : m0;
                float bi = half ? bi1 : bi0;
                float2 v2;
                v2.x = acc[mi][n8][2 * half + 0] + bi;
                v2.y = acc[mi][n8][2 * half + 1] + bi;
                *(float2*)&Y[((size_t)b * 256 + mm) * 1024 + n] = v2;
            }
        }
    }
}

// ---------------------------------------------------------------------------
// Flash attention, pure fp16: 64 q-rows per CTA (16/warp). 128-key staging
// (8 barrier rounds) computed as two 64-key halves (keeps live regs low).
// smem: Q 5KB + 2 stages x 20KB = 45KB -> 4 CTAs/SM.
// ---------------------------------------------------------------------------
#define Q_S 0
#define KV_S 5120
#define KV_STAGE 20480
#define ATT_SMEM 46080

__global__ void __launch_bounds__(128, 4) attn_hmma()
{
    extern __shared__ char smc[];
    const uint32_t sb = smem_u32(smc);
    const int tid = threadIdx.x, lane = tid & 31, warp = tid >> 5;
    const int pair = blockIdx.y;
    const int qBase = blockIdx.x * 64;

    const char* q_g = (const char*)(g_q + ((size_t)pair * 1024 + qBase) * 32);
    const char* k_g = (const char*)(g_k + (size_t)pair * 1024 * 32);
    const char* v_g = (const char*)(g_v + (size_t)pair * 1024 * 32);

    // Q: 64 rows x 64B = 256 chunks
#pragma unroll
    for (int i = 0; i < 2; i++) {
        int c = tid + i * 128;
        int row = c >> 2, part = c & 3;
        cp16(sb + Q_S + (uint32_t)row * 80 + (uint32_t)part * 16, q_g + row * 64 + part * 16);
    }

    // stage 128 keys (K 10240B + V 10240B): 512 chunks each array
#define KV_LOAD(t, s)                                                          \
    {                                                                          \
        uint32_t base_ = sb + KV_S + (uint32_t)(s) * KV_STAGE;                 \
        size_t go_ = (size_t)(t) * 128 * 64;                                   \
        _Pragma("unroll")                                                      \
        for (int i_ = 0; i_ < 4; i_++) {                                       \
            int c_ = tid + i_ * 128;                                           \
            int row_ = c_ >> 2, part_ = c_ & 3;                                \
            uint32_t doff_ = (uint32_t)row_ * 80 + (uint32_t)part_ * 16;       \
            size_t so_ = go_ + row_ * 64 + part_ * 16;                         \
            cp16(base_ + 0     + doff_, k_g + so_);                            \
            cp16(base_ + 10240 + doff_, v_g + so_);                            \
        }                                                                      \
    }

    KV_LOAD(0, 0); CP_COMMIT();
    CP_WAIT0(); __syncthreads();

    uint32_t qf[2][4];
    {
        uint32_t r = (uint32_t)(warp * 16 + (lane & 15));
        uint32_t cb = (uint32_t)((lane >> 4) & 1) * 16;
        ldm_x4(qf[0], sb + Q_S + r * 80 + cb);
        ldm_x4(qf[1], sb + Q_S + r * 80 + 32 + cb);
    }

    float o[4][4];
#pragma unroll
    for (int i = 0; i < 4; i++)
#pragma unroll
        for (int r = 0; r < 4; r++) o[i][r] = 0.f;
    float rsum[4] = {0.f, 0.f, 0.f, 0.f};

    const uint32_t onesb[2] = {0x3C003C00u, 0x3C003C00u};
    const uint32_t bRow = (uint32_t)((lane & 7) + ((lane >> 4) & 1) * 8);
    const uint32_t bColK = (uint32_t)((lane >> 3) & 1) * 16;
    const uint32_t vRow = (uint32_t)((lane & 7) + ((lane >> 3) & 1) * 8);
    const uint32_t vColB = (uint32_t)((lane >> 4) & 1) * 16;

    for (int t = 0; t < 8; t++) {
        if (t < 7) { KV_LOAD(t + 1, (t + 1) & 1); CP_COMMIT(); }
        const uint32_t kb = sb + KV_S + (uint32_t)(t & 1) * KV_STAGE;

#pragma unroll
        for (int hB = 0; hB < 2; hB++) {
            const uint32_t rowOff = (uint32_t)(hB * 64);
            float s[8][4];
#pragma unroll
            for (int j = 0; j < 8; j++)
#pragma unroll
                for (int r = 0; r < 4; r++) s[j][r] = 0.f;

            // ---- S = Q K^T (64 keys) ----
#pragma unroll
            for (int kg = 0; kg < 4; kg++) {
                uint32_t base = (rowOff + (uint32_t)(kg * 16) + bRow) * 80 + bColK;
                uint32_t k0f[4], k1f[4];
                ldm_x4(k0f, kb + base);
                ldm_x4(k1f, kb + base + 32);
#pragma unroll
                for (int gs = 0; gs < 2; gs++) {
                    float* sj = s[2 * kg + gs];
                    mma_f16(sj, qf[0], &k0f[2 * gs]);
                    mma_f16(sj, qf[1], &k1f[2 * gs]);
                }
            }

            // ---- O += P V; row sums via ones-MMA ----
#pragma unroll
            for (int kc = 0; kc < 4; kc++) {
                uint32_t vbase = (rowOff + (uint32_t)(kc * 16) + vRow) * 80 + vColB;
                uint32_t v0f[4], v1f[4];
                ldm_x4t(v0f, kb + 10240 + vbase);
                ldm_x4t(v1f, kb + 10240 + vbase + 32);
                uint32_t ph[4];
                ph[0] = ex2_h2(pack_h2(s[2 * kc][0],     s[2 * kc][1]));
                ph[1] = ex2_h2(pack_h2(s[2 * kc][2],     s[2 * kc][3]));
                ph[2] = ex2_h2(pack_h2(s[2 * kc + 1][0], s[2 * kc + 1][1]));
                ph[3] = ex2_h2(pack_h2(s[2 * kc + 1][2], s[2 * kc + 1][3]));
                mma_f16(o[0], ph, &v0f[0]); mma_f16(o[1], ph, &v0f[2]);
                mma_f16(o[2], ph, &v1f[0]); mma_f16(o[3], ph, &v1f[2]);
                mma_f16(rsum, ph, onesb);
            }
        }
        if (t < 7) { CP_WAIT0(); __syncthreads(); }
    }
#undef KV_LOAD

    // ---- normalize + store fp16 O [b,n,cv] ----
    const int g = lane >> 2, t4 = lane & 3;
    const int bb = pair >> 3, hh = pair & 7;
    uint32_t* op = (uint32_t*)g_o;
    const float inv0 = 1.0f / rsum[0], inv1 = 1.0f / rsum[2];
    const size_t r0g = qBase + warp * 16 + g;
    const size_t r1g = r0g + 8;
#pragma unroll
    for (int nt = 0; nt < 4; nt++) {
        int d = nt * 8 + t4 * 2;
        size_t i0 = (((size_t)bb * 1024 + r0g) * 256 + hh * 32 + d) >> 1;
        size_t i1 = (((size_t)bb * 1024 + r1g) * 256 + hh * 32 + d) >> 1;
        op[i0] = pack_h2(o[nt][0] * inv0, o[nt][1] * inv0);
        op[i1] = pack_h2(o[nt][2] * inv1, o[nt][3] * inv1);
    }
}

// ---------------------------------------------------------------------------
extern "C" void kernel_launch(void* const* d_in, const int* in_sizes, int n_in,
                              void* d_out, int out_size)
{
    const float* x  = (const float*)d_in[0];
    const float* Wq = (const float*)d_in[1];
    const float* bq = (const float*)d_in[2];
    const float* Wk = (const float*)d_in[3];
    const float* bk = (const float*)d_in[4];
    const float* Wv = (const float*)d_in[5];
    const float* bv = (const float*)d_in[6];
    const float* Wo = (const float*)d_in[7];
    const float* bo = (const float*)d_in[8];
    float* out = (float*)d_out;

    cudaFuncSetAttribute(qkv_gemm, cudaFuncAttributeMaxDynamicSharedMemorySize, GEMM_SMEM);
    cudaFuncSetAttribute(out_gemm, cudaFuncAttributeMaxDynamicSharedMemorySize, GEMM_SMEM);
    cudaFuncSetAttribute(attn_hmma, cudaFuncAttributeMaxDynamicSharedMemorySize, ATT_SMEM);

    prep_all<<<3072, 256>>>(x, Wq, Wk, Wv, Wo);
    qkv_gemm<<<dim3(8, 4, 24), 256, GEMM_SMEM>>>(bq, bk, bv);
    attn_hmma<<<dim3(16, 64), 128, ATT_SMEM>>>();
    out_gemm<<<dim3(8, 4, 8), 256, GEMM_SMEM>>>(bo, out);
}

// round 15
// speedup vs baseline: 1.0019x; 1.0019x over previous
#include <cuda_runtime.h>
#include <cuda_fp16.h>
#include <cstdint>

// Problem: B=8, C=256, H=W=32 -> N=1024, heads=8, dk=dv=32.

// ---------------- helpers ----------------
__device__ __forceinline__ uint32_t smem_u32(const void* p) {
    uint32_t a;
    asm("{ .reg .u64 t; cvta.to.shared.u64 t, %1; cvt.u32.u64 %0, t; }" : "=r"(a) : "l"(p));
    return a;
}
__device__ __forceinline__ void ldm_x4(uint32_t r[4], uint32_t addr) {
    asm volatile("ldmatrix.sync.aligned.m8n8.x4.shared.b16 {%0,%1,%2,%3}, [%4];"
                 : "=r"(r[0]), "=r"(r[1]), "=r"(r[2]), "=r"(r[3]) : "r"(addr));
}
__device__ __forceinline__ void ldm_x4t(uint32_t r[4], uint32_t addr) {
    asm volatile("ldmatrix.sync.aligned.m8n8.x4.trans.shared.b16 {%0,%1,%2,%3}, [%4];"
                 : "=r"(r[0]), "=r"(r[1]), "=r"(r[2]), "=r"(r[3]) : "r"(addr));
}
__device__ __forceinline__ void mma_f16(float* c, const uint32_t* a, const uint32_t* b) {
    asm volatile(
        "mma.sync.aligned.m16n8k16.row.col.f32.f16.f16.f32 "
        "{%0,%1,%2,%3}, {%4,%5,%6,%7}, {%8,%9}, {%0,%1,%2,%3};"
        : "+f"(c[0]), "+f"(c[1]), "+f"(c[2]), "+f"(c[3])
        : "r"(a[0]), "r"(a[1]), "r"(a[2]), "r"(a[3]), "r"(b[0]), "r"(b[1]));
}
__device__ __forceinline__ uint32_t pack_h2(float x, float y) {
    __half2 p = __float22half2_rn(make_float2(x, y));
    return *(uint32_t*)&p;
}
__device__ __forceinline__ uint32_t ex2_h2(uint32_t x) {
    uint32_t y; asm("ex2.approx.f16x2 %0, %1;" : "=r"(y) : "r"(x)); return y;
}
__device__ __forceinline__ void cp16(uint32_t dst, const void* src) {
    asm volatile("cp.async.cg.shared.global [%0], [%1], 16;" :: "r"(dst), "l"(src));
}
#define CP_COMMIT() asm volatile("cp.async.commit_group;" ::: "memory")
#define CP_WAIT(n)  asm volatile("cp.async.wait_group %0;" :: "n"(n) : "memory")

// ---------------- scratch ----------------
__device__ __half g_wh[4 * 65536], g_wl[4 * 65536];   // Wq,Wk,Wv,Wo [m][k] hi/lo
__device__ __half g_xt[8*1024*256];                   // [b, n, c] pure fp16
__device__ __half g_q [8*8*1024*32];                  // [b,h,n,d] pure (scaled)
__device__ __half g_k [8*8*1024*32];                  // [b,h,n,d] pure
__device__ __half g_v [8*8*1024*32];                  // [b,h,n,d] pure
__device__ __half g_o [8*1024*256];                   // [b,n,cv] pure

// ---------------------------------------------------------------------------
// Fused prep: blocks 0..2047 transpose x -> xT fp16; 2048..3071 split weights.
// ---------------------------------------------------------------------------
__global__ void __launch_bounds__(256) prep_all(
    const float* __restrict__ x,
    const float* __restrict__ Wq, const float* __restrict__ Wk,
    const float* __restrict__ Wv, const float* __restrict__ Wo)
{
    __shared__ float tile[32][33];
    const int blk = blockIdx.x;
    const int tid = threadIdx.x;
    if (blk < 2048) {
        const int nblk = blk & 31, cblk = (blk >> 5) & 7, b = blk >> 8;
        const int n0 = nblk * 32, c0 = cblk * 32;
        const int tx = tid & 31, ty = tid >> 5;
#pragma unroll
        for (int i = 0; i < 4; i++)
            tile[ty + 8 * i][tx] = x[((size_t)b * 256 + c0 + ty + 8 * i) * 1024 + n0 + tx];
        __syncthreads();
#pragma unroll
        for (int i = 0; i < 4; i++)
            g_xt[((size_t)b * 1024 + n0 + ty + 8 * i) * 256 + c0 + tx] =
                __float2half_rn(tile[tx][ty + 8 * i]);
    } else {
        int idx = (blk - 2048) * 256 + tid;
        int sel = idx >> 16, off = idx & 65535;
        const float* W = sel == 0 ? Wq : (sel == 1 ? Wk : (sel == 2 ? Wv : Wo));
        float v = W[off];
        __half h = __float2half_rn(v);
        g_wh[idx] = h;
        g_wl[idx] = __float2half_rn(v - __half2float(h));
    }
}

// ---------------------------------------------------------------------------
// GEMM core: acc += W[(MI*32)m x 256k] * X[128n x 256k]^T, TERMS in {1,2}.
// 4-stage cp.async pipeline over 8 K-chunks of 32 (3 chunks in flight).
// Pitch-80 rows (64B data), conflict-free ldmatrix.
// ---------------------------------------------------------------------------
#define LDR 80
#define GEMM_SMEM 81920

template<int TERMS, int MI>
__device__ __forceinline__ void gemm_stage(
    const __half* __restrict__ Ah, const __half* __restrict__ Al,
    const __half* __restrict__ Bx,
    int mBase, int nBase, uint32_t sb, int tid, int kc, int s)
{
    constexpr uint32_t A_BYTES = (uint32_t)MI * 32 * LDR;
    constexpr uint32_t B_OFF   = A_BYTES * TERMS;
    constexpr uint32_t STAGE   = B_OFF + 128 * LDR;
    constexpr int A_ROWS = MI * 32;
    constexpr int ITERS = (A_ROWS * TERMS + 128) * 4 / 256;

    uint32_t base = sb + (uint32_t)s * STAGE;
#pragma unroll
    for (int i = 0; i < ITERS; i++) {
        int idx = tid + i * 256;
        int r = idx >> 2, part = idx & 3;
        uint32_t cOff = (uint32_t)part * 16;
        if (r < A_ROWS) {
            cp16(base + (uint32_t)r * LDR + cOff,
                 Ah + (size_t)(mBase + r) * 256 + kc * 32 + part * 8);
        } else if (TERMS == 2 && r < 2 * A_ROWS) {
            int rr = r - A_ROWS;
            cp16(base + A_BYTES + (uint32_t)rr * LDR + cOff,
                 Al + (size_t)(mBase + rr) * 256 + kc * 32 + part * 8);
        } else {
            int rr = r - A_ROWS * TERMS;
            cp16(base + B_OFF + (uint32_t)rr * LDR + cOff,
                 Bx + (size_t)(nBase + rr) * 256 + kc * 32 + part * 8);
        }
    }
}

template<int TERMS, int MI>
__device__ __forceinline__ void gemm_run(
    const __half* __restrict__ Ah, const __half* __restrict__ Al,
    const __half* __restrict__ Bx,
    int mBase, int nBase, uint32_t sb,
    int warpM, int warpN, int lane, int tid, float acc[MI][4][4])
{
    constexpr uint32_t A_BYTES = (uint32_t)MI * 32 * LDR;
    constexpr uint32_t AL_OFF  = A_BYTES;
    constexpr uint32_t B_OFF   = A_BYTES * TERMS;
    constexpr uint32_t STAGE   = B_OFF + 128 * LDR;

    const uint32_t aRow = (uint32_t)(lane & 15);
    const uint32_t aCol = (uint32_t)((lane >> 4) & 1) * 16;
    const uint32_t bRow = (uint32_t)((lane & 7) + ((lane >> 4) & 1) * 8);
    const uint32_t bCol = (uint32_t)((lane >> 3) & 1) * 16;

    // prologue: fill 3 of 4 stages
    gemm_stage<TERMS, MI>(Ah, Al, Bx, mBase, nBase, sb, tid, 0, 0); CP_COMMIT();
    gemm_stage<TERMS, MI>(Ah, Al, Bx, mBase, nBase, sb, tid, 1, 1); CP_COMMIT();
    gemm_stage<TERMS, MI>(Ah, Al, Bx, mBase, nBase, sb, tid, 2, 2); CP_COMMIT();

    for (int kc = 0; kc < 8; kc++) {
        CP_WAIT(2);            // chunk kc complete (<=2 newer groups pending)
        __syncthreads();
        if (kc + 3 < 8) {      // buffer (kc+3)&3 == (kc-1)&3, consumed, safe
            gemm_stage<TERMS, MI>(Ah, Al, Bx, mBase, nBase, sb, tid, kc + 3, (kc + 3) & 3);
            CP_COMMIT();
        }
        const uint32_t kb = sb + (uint32_t)(kc & 3) * STAGE;
#pragma unroll
        for (int ks = 0; ks < 2; ks++) {
            const uint32_t kOff = (uint32_t)ks * 32;
            uint32_t af[MI][4], bf[2][4];
#pragma unroll
            for (int nj = 0; nj < 2; nj++) {
                uint32_t row = (uint32_t)(warpN * 32 + nj * 16) + bRow;
                ldm_x4(bf[nj], kb + B_OFF + row * LDR + kOff + bCol);
            }
#pragma unroll
            for (int mi = 0; mi < MI; mi++) {
                uint32_t row = (uint32_t)(warpM * MI * 16 + mi * 16) + aRow;
                ldm_x4(af[mi], kb + row * LDR + kOff + aCol);
            }
#pragma unroll
            for (int mi = 0; mi < MI; mi++)
#pragma unroll
                for (int nj = 0; nj < 2; nj++) {
                    mma_f16(acc[mi][2 * nj + 0], af[mi], &bf[nj][0]);
                    mma_f16(acc[mi][2 * nj + 1], af[mi], &bf[nj][2]);
                }
            if (TERMS == 2) {
#pragma unroll
                for (int mi = 0; mi < MI; mi++) {
                    uint32_t row = (uint32_t)(warpM * MI * 16 + mi * 16) + aRow;
                    ldm_x4(af[mi], kb + AL_OFF + row * LDR + kOff + aCol);
                }
#pragma unroll
                for (int mi = 0; mi < MI; mi++)
#pragma unroll
                    for (int nj = 0; nj < 2; nj++) {
                        mma_f16(acc[mi][2 * nj + 0], af[mi], &bf[nj][0]);
                        mma_f16(acc[mi][2 * nj + 1], af[mi], &bf[nj][2]);
                    }
            }
        }
    }
}

// ---------------------------------------------------------------------------
// QKV projection: 64m x 128n tiles, grid (8,4,24). Q/K 2-term, V 1-term.
// Q scale includes 1/sqrt(dk) * log2(e).
// ---------------------------------------------------------------------------
__global__ void __launch_bounds__(256, 2) qkv_gemm(
    const float* __restrict__ bq, const float* __restrict__ bk,
    const float* __restrict__ bv)
{
    extern __shared__ char smc[];
    const uint32_t sb = smem_u32(smc);
    const int tid = threadIdx.x, lane = tid & 31, wid = tid >> 5;
    const int z = blockIdx.z, b = z / 3, sel = z - 3 * b;
    const int mBase = blockIdx.y * 64;
    const int nBase = blockIdx.x * 128;
    const int warpM = wid >> 2, warpN = wid & 3;

    const float* bias = sel == 0 ? bq : (sel == 1 ? bk : bv);
    const float scale = sel == 0 ? 0.17677669529663687f * 1.4426950408889634f : 1.0f;
    __half* Yp = sel == 0 ? g_q : (sel == 1 ? g_k : g_v);

    float acc[2][4][4];
#pragma unroll
    for (int i = 0; i < 2; i++)
#pragma unroll
        for (int j = 0; j < 4; j++)
#pragma unroll
            for (int r = 0; r < 4; r++) acc[i][j][r] = 0.f;

    const __half* Xb = g_xt + (size_t)b * 1024 * 256;
    if (sel == 2)
        gemm_run<1, 2>(g_wh + 2 * 65536, nullptr, Xb,
                       mBase, nBase, sb, warpM, warpN, lane, tid, acc);
    else
        gemm_run<2, 2>(g_wh + sel * 65536, g_wl + sel * 65536, Xb,
                       mBase, nBase, sb, warpM, warpN, lane, tid, acc);

    const int g = lane >> 2, t4 = lane & 3;
#pragma unroll
    for (int mi = 0; mi < 2; mi++) {
        int m0 = mBase + warpM * 32 + mi * 16 + g;
        float bi0 = bias[m0], bi1 = bias[m0 + 8];
#pragma unroll
        for (int n8 = 0; n8 < 4; n8++) {
            int n = nBase + warpN * 32 + n8 * 8 + t4 * 2;
#pragma unroll
            for (int half = 0; half < 2; half++) {
                int mm = half ? m0 + 8 : m0;
                float bi = half ? bi1 : bi0;
                float v0 = (acc[mi][n8][2 * half + 0] + bi) * scale;
                float v1 = (acc[mi][n8][2 * half + 1] + bi) * scale;
                size_t base = (((size_t)b * 8 + (mm >> 5)) * 1024 + n) * 32 + (mm & 31);
                Yp[base] = __float2half_rn(v0);
                Yp[base + 32] = __float2half_rn(v1);
            }
        }
    }
}

// ---------------------------------------------------------------------------
// Output projection: 64m x 128n tiles, grid (8,4,8). 2-term. fp32 out [b,c,n].
// ---------------------------------------------------------------------------
__global__ void __launch_bounds__(256, 2) out_gemm(
    const float* __restrict__ bo, float* __restrict__ Y)
{
    extern __shared__ char smc[];
    const uint32_t sb = smem_u32(smc);
    const int tid = threadIdx.x, lane = tid & 31, wid = tid >> 5;
    const int b = blockIdx.z;
    const int mBase = blockIdx.y * 64;
    const int nBase = blockIdx.x * 128;
    const int warpM = wid >> 2, warpN = wid & 3;

    float acc[2][4][4];
#pragma unroll
    for (int i = 0; i < 2; i++)
#pragma unroll
        for (int j = 0; j < 4; j++)
#pragma unroll
            for (int r = 0; r < 4; r++) acc[i][j][r] = 0.f;

    gemm_run<2, 2>(g_wh + 3 * 65536, g_wl + 3 * 65536,
                   g_o + (size_t)b * 1024 * 256,
                   mBase, nBase, sb, warpM, warpN, lane, tid, acc);

    const int g = lane >> 2, t4 = lane & 3;
#pragma unroll
    for (int mi = 0; mi < 2; mi++) {
        int m0 = mBase + warpM * 32 + mi * 16 + g;
        float bi0 = bo[m0], bi1 = bo[m0 + 8];
#pragma unroll
        for (int n8 = 0; n8 < 4; n8++) {
            int n = nBase + warpN * 32 + n8 * 8 + t4 * 2;
#pragma unroll
            for (int half = 0; half < 2; half++) {
                int mm = half ? m0 + 8 : m0;
                float bi = half ? bi1 : bi0;
                float2 v2;
                v2.x = acc[mi][n8][2 * half + 0] + bi;
                v2.y = acc[mi][n8][2 * half + 1] + bi;
                *(float2*)&Y[((size_t)b * 256 + mm) * 1024 + n] = v2;
            }
        }
    }
}

// ---------------------------------------------------------------------------
// Flash attention, pure fp16: 64 q-rows per CTA (16/warp), 64-key tiles,
// 3-stage cp.async pipeline (2 tiles in flight), ones-MMA row sums.
// smem: Q 5KB + 3 stages x 10KB = 35KB -> 4 CTAs/SM.
// ---------------------------------------------------------------------------
#define Q_S 0
#define KV_S 5120
#define KV_STAGE 10240
#define ATT_SMEM 35840

__global__ void __launch_bounds__(128, 4) attn_hmma()
{
    extern __shared__ char smc[];
    const uint32_t sb = smem_u32(smc);
    const int tid = threadIdx.x, lane = tid & 31, warp = tid >> 5;
    const int pair = blockIdx.y;
    const int qBase = blockIdx.x * 64;

    const char* q_g = (const char*)(g_q + ((size_t)pair * 1024 + qBase) * 32);
    const char* k_g = (const char*)(g_k + (size_t)pair * 1024 * 32);
    const char* v_g = (const char*)(g_v + (size_t)pair * 1024 * 32);

    // Q: 64 rows x 64B = 256 chunks
#pragma unroll
    for (int i = 0; i < 2; i++) {
        int c = tid + i * 128;
        int row = c >> 2, part = c & 3;
        cp16(sb + Q_S + (uint32_t)row * 80 + (uint32_t)part * 16, q_g + row * 64 + part * 16);
    }

#define KV_LOAD(t, s)                                                          \
    {                                                                          \
        uint32_t base_ = sb + KV_S + (uint32_t)(s) * KV_STAGE;                 \
        size_t go_ = (size_t)(t) * 64 * 64;                                    \
        _Pragma("unroll")                                                      \
        for (int i_ = 0; i_ < 2; i_++) {                                       \
            int c_ = tid + i_ * 128;                                           \
            int row_ = c_ >> 2, part_ = c_ & 3;                                \
            uint32_t doff_ = (uint32_t)row_ * 80 + (uint32_t)part_ * 16;       \
            size_t so_ = go_ + row_ * 64 + part_ * 16;                         \
            cp16(base_ + 0    + doff_, k_g + so_);                             \
            cp16(base_ + 5120 + doff_, v_g + so_);                             \
        }                                                                      \
    }

    // prologue: Q + tile 0 in group 0, tile 1 in group 1
    KV_LOAD(0, 0); CP_COMMIT();
    KV_LOAD(1, 1); CP_COMMIT();

    CP_WAIT(1); __syncthreads();

    // hoist Q fragments: 16 rows per warp
    uint32_t qf[2][4];
    {
        uint32_t r = (uint32_t)(warp * 16 + (lane & 15));
        uint32_t cb = (uint32_t)((lane >> 4) & 1) * 16;
        ldm_x4(qf[0], sb + Q_S + r * 80 + cb);
        ldm_x4(qf[1], sb + Q_S + r * 80 + 32 + cb);
    }

    float o[4][4];
#pragma unroll
    for (int i = 0; i < 4; i++)
#pragma unroll
        for (int r = 0; r < 4; r++) o[i][r] = 0.f;
    float rsum[4] = {0.f, 0.f, 0.f, 0.f};

    const uint32_t onesb[2] = {0x3C003C00u, 0x3C003C00u};
    const uint32_t bRow = (uint32_t)((lane & 7) + ((lane >> 4) & 1) * 8);
    const uint32_t bColK = (uint32_t)((lane >> 3) & 1) * 16;
    const uint32_t vRow = (uint32_t)((lane & 7) + ((lane >> 3) & 1) * 8);
    const uint32_t vColB = (uint32_t)((lane >> 4) & 1) * 16;

    for (int t = 0; t < 16; t++) {
        if (t) { CP_WAIT(1); __syncthreads(); }
        if (t + 2 < 16) { KV_LOAD(t + 2, (t + 2) % 3); CP_COMMIT(); }
        const uint32_t kb = sb + KV_S + (uint32_t)(t % 3) * KV_STAGE;

        float s[8][4];
#pragma unroll
        for (int j = 0; j < 8; j++)
#pragma unroll
            for (int r = 0; r < 4; r++) s[j][r] = 0.f;

        // ---- S = Q K^T ----
#pragma unroll
        for (int kg = 0; kg < 4; kg++) {
            uint32_t base = ((uint32_t)(kg * 16) + bRow) * 80 + bColK;
            uint32_t k0f[4], k1f[4];
            ldm_x4(k0f, kb + base);
            ldm_x4(k1f, kb + base + 32);
#pragma unroll
            for (int gs = 0; gs < 2; gs++) {
                float* sj = s[2 * kg + gs];
                mma_f16(sj, qf[0], &k0f[2 * gs]);
                mma_f16(sj, qf[1], &k1f[2 * gs]);
            }
        }

        // ---- O += P V; row sums via ones-MMA ----
#pragma unroll
        for (int kc = 0; kc < 4; kc++) {
            uint32_t vbase = ((uint32_t)(kc * 16) + vRow) * 80 + vColB;
            uint32_t v0f[4], v1f[4];
            ldm_x4t(v0f, kb + 5120 + vbase);
            ldm_x4t(v1f, kb + 5120 + vbase + 32);
            uint32_t ph[4];
            ph[0] = ex2_h2(pack_h2(s[2 * kc][0],     s[2 * kc][1]));
            ph[1] = ex2_h2(pack_h2(s[2 * kc][2],     s[2 * kc][3]));
            ph[2] = ex2_h2(pack_h2(s[2 * kc + 1][0], s[2 * kc + 1][1]));
            ph[3] = ex2_h2(pack_h2(s[2 * kc + 1][2], s[2 * kc + 1][3]));
            mma_f16(o[0], ph, &v0f[0]); mma_f16(o[1], ph, &v0f[2]);
            mma_f16(o[2], ph, &v1f[0]); mma_f16(o[3], ph, &v1f[2]);
            mma_f16(rsum, ph, onesb);
        }
    }
#undef KV_LOAD

    // ---- normalize + store fp16 O [b,n,cv]; rsum[0]=row r0, rsum[2]=row r1 ----
    const int g = lane >> 2, t4 = lane & 3;
    const int bb = pair >> 3, hh = pair & 7;
    uint32_t* op = (uint32_t*)g_o;
    const float inv0 = 1.0f / rsum[0], inv1 = 1.0f / rsum[2];
    const size_t r0g = qBase + warp * 16 + g;
    const size_t r1g = r0g + 8;
#pragma unroll
    for (int nt = 0; nt < 4; nt++) {
        int d = nt * 8 + t4 * 2;
        size_t i0 = (((size_t)bb * 1024 + r0g) * 256 + hh * 32 + d) >> 1;
        size_t i1 = (((size_t)bb * 1024 + r1g) * 256 + hh * 32 + d) >> 1;
        op[i0] = pack_h2(o[nt][0] * inv0, o[nt][1] * inv0);
        op[i1] = pack_h2(o[nt][2] * inv1, o[nt][3] * inv1);
    }
}

// ---------------------------------------------------------------------------
extern "C" void kernel_launch(void* const* d_in, const int* in_sizes, int n_in,
                              void* d_out, int out_size)
{
    const float* x  = (const float*)d_in[0];
    const float* Wq = (const float*)d_in[1];
    const float* bq = (const float*)d_in[2];
    const float* Wk = (const float*)d_in[3];
    const float* bk = (const float*)d_in[4];
    const float* Wv = (const float*)d_in[5];
    const float* bv = (const float*)d_in[6];
    const float* Wo = (const float*)d_in[7];
    const float* bo = (const float*)d_in[8];
    float* out = (float*)d_out;

    cudaFuncSetAttribute(qkv_gemm, cudaFuncAttributeMaxDynamicSharedMemorySize, GEMM_SMEM);
    cudaFuncSetAttribute(out_gemm, cudaFuncAttributeMaxDynamicSharedMemorySize, GEMM_SMEM);
    cudaFuncSetAttribute(attn_hmma, cudaFuncAttributeMaxDynamicSharedMemorySize, ATT_SMEM);

    prep_all<<<3072, 256>>>(x, Wq, Wk, Wv, Wo);
    qkv_gemm<<<dim3(8, 4, 24), 256, GEMM_SMEM>>>(bq, bk, bv);
    attn_hmma<<<dim3(16, 64), 128, ATT_SMEM>>>();
    out_gemm<<<dim3(8, 4, 8), 256, GEMM_SMEM>>>(bo, out);
}

// round 16
// speedup vs baseline: 1.0216x; 1.0197x over previous
#include <cuda_runtime.h>
#include <cuda_fp16.h>
#include <cstdint>

// Problem: B=8, C=256, H=W=32 -> N=1024, heads=8, dk=dv=32.

// ---------------- helpers ----------------
__device__ __forceinline__ uint32_t smem_u32(const void* p) {
    uint32_t a;
    asm("{ .reg .u64 t; cvta.to.shared.u64 t, %1; cvt.u32.u64 %0, t; }" : "=r"(a) : "l"(p));
    return a;
}
__device__ __forceinline__ void ldm_x4(uint32_t r[4], uint32_t addr) {
    asm volatile("ldmatrix.sync.aligned.m8n8.x4.shared.b16 {%0,%1,%2,%3}, [%4];"
                 : "=r"(r[0]), "=r"(r[1]), "=r"(r[2]), "=r"(r[3]) : "r"(addr));
}
__device__ __forceinline__ void ldm_x4t(uint32_t r[4], uint32_t addr) {
    asm volatile("ldmatrix.sync.aligned.m8n8.x4.trans.shared.b16 {%0,%1,%2,%3}, [%4];"
                 : "=r"(r[0]), "=r"(r[1]), "=r"(r[2]), "=r"(r[3]) : "r"(addr));
}
__device__ __forceinline__ void mma_f16(float* c, const uint32_t* a, const uint32_t* b) {
    asm volatile(
        "mma.sync.aligned.m16n8k16.row.col.f32.f16.f16.f32 "
        "{%0,%1,%2,%3}, {%4,%5,%6,%7}, {%8,%9}, {%0,%1,%2,%3};"
        : "+f"(c[0]), "+f"(c[1]), "+f"(c[2]), "+f"(c[3])
        : "r"(a[0]), "r"(a[1]), "r"(a[2]), "r"(a[3]), "r"(b[0]), "r"(b[1]));
}
__device__ __forceinline__ uint32_t pack_h2(float x, float y) {
    __half2 p = __float22half2_rn(make_float2(x, y));
    return *(uint32_t*)&p;
}
__device__ __forceinline__ uint32_t ex2_h2(uint32_t x) {
    uint32_t y; asm("ex2.approx.f16x2 %0, %1;" : "=r"(y) : "r"(x)); return y;
}
__device__ __forceinline__ void cp16(uint32_t dst, const void* src) {
    asm volatile("cp.async.cg.shared.global [%0], [%1], 16;" :: "r"(dst), "l"(src));
}
#define CP_COMMIT() asm volatile("cp.async.commit_group;" ::: "memory")
#define CP_WAIT0()  asm volatile("cp.async.wait_group 0;" ::: "memory")

// ---------------- scratch ----------------
__device__ __half g_wh[4 * 65536], g_wl[4 * 65536];   // Wq,Wk,Wv,Wo [m][k] hi/lo
__device__ __half g_xt[8*1024*256];                   // [b, n, c] pure fp16
__device__ __half g_q [8*8*1024*32];                  // [b,h,n,d] pure (scaled)
__device__ __half g_k [8*8*1024*32];                  // [b,h,n,d] pure
__device__ __half g_v [8*8*1024*32];                  // [b,h,n,d] pure
__device__ __half g_o [8*1024*256];                   // [b,n,cv] pure

// ---------------------------------------------------------------------------
// Fused prep: blocks 0..2047 transpose x -> xT fp16; 2048..3071 split weights.
// ---------------------------------------------------------------------------
__global__ void __launch_bounds__(256) prep_all(
    const float* __restrict__ x,
    const float* __restrict__ Wq, const float* __restrict__ Wk,
    const float* __restrict__ Wv, const float* __restrict__ Wo)
{
    __shared__ float tile[32][33];
    const int blk = blockIdx.x;
    const int tid = threadIdx.x;
    if (blk < 2048) {
        const int nblk = blk & 31, cblk = (blk >> 5) & 7, b = blk >> 8;
        const int n0 = nblk * 32, c0 = cblk * 32;
        const int tx = tid & 31, ty = tid >> 5;
#pragma unroll
        for (int i = 0; i < 4; i++)
            tile[ty + 8 * i][tx] = x[((size_t)b * 256 + c0 + ty + 8 * i) * 1024 + n0 + tx];
        __syncthreads();
#pragma unroll
        for (int i = 0; i < 4; i++)
            g_xt[((size_t)b * 1024 + n0 + ty + 8 * i) * 256 + c0 + tx] =
                __float2half_rn(tile[tx][ty + 8 * i]);
    } else {
        int idx = (blk - 2048) * 256 + tid;     // 0..262143
        int sel = idx >> 16, off = idx & 65535;
        const float* W = sel == 0 ? Wq : (sel == 1 ? Wk : (sel == 2 ? Wv : Wo));
        float v = W[off];
        __half h = __float2half_rn(v);
        g_wh[idx] = h;
        g_wl[idx] = __float2half_rn(v - __half2float(h));
    }
}

// ---------------------------------------------------------------------------
// GEMM core: acc += W[64m x 256k] * X[64n x 256k]^T, TERMS in {1,2}.
// 128-thread CTA, 4 warps as 2m x 2n (warp tile 32m x 32n), MI=2.
// K-chunks of 64 (pitch-144, conflict-free ldmatrix), double-buffered,
// 4 barrier rounds. smem 2 x 27.6KB -> 4 CTAs/SM.
// ---------------------------------------------------------------------------
#define LDR 144
#define GEMM_SMEM 55296

template<int TERMS>
__device__ __forceinline__ void gemm_stage(
    const __half* __restrict__ Ah, const __half* __restrict__ Al,
    const __half* __restrict__ Bx,
    int mBase, int nBase, uint32_t sb, int tid, int kc, int s)
{
    constexpr uint32_t A_BYTES = 64u * LDR;               // 64 A rows per term
    constexpr uint32_t B_OFF   = A_BYTES * TERMS;
    constexpr uint32_t STAGE   = B_OFF + 64 * LDR;
    constexpr int ROWS  = 64 * TERMS + 64;
    constexpr int ITERS = ROWS * 8 / 128;                 // 8 chunks per row

    uint32_t base = sb + (uint32_t)s * STAGE;
#pragma unroll
    for (int i = 0; i < ITERS; i++) {
        int idx = tid + i * 128;
        int r = idx >> 3, part = idx & 7;
        uint32_t cOff = (uint32_t)part * 16;
        if (r < 64) {
            cp16(base + (uint32_t)r * LDR + cOff,
                 Ah + (size_t)(mBase + r) * 256 + kc * 64 + part * 8);
        } else if (TERMS == 2 && r < 128) {
            int rr = r - 64;
            cp16(base + A_BYTES + (uint32_t)rr * LDR + cOff,
                 Al + (size_t)(mBase + rr) * 256 + kc * 64 + part * 8);
        } else {
            int rr = r - 64 * TERMS;
            cp16(base + B_OFF + (uint32_t)rr * LDR + cOff,
                 Bx + (size_t)(nBase + rr) * 256 + kc * 64 + part * 8);
        }
    }
}

template<int TERMS>
__device__ __forceinline__ void gemm_run(
    const __half* __restrict__ Ah, const __half* __restrict__ Al,
    const __half* __restrict__ Bx,
    int mBase, int nBase, uint32_t sb,
    int warpM, int warpN, int lane, int tid, float acc[2][4][4])
{
    constexpr uint32_t A_BYTES = 64u * LDR;
    constexpr uint32_t AL_OFF  = A_BYTES;
    constexpr uint32_t B_OFF   = A_BYTES * TERMS;
    constexpr uint32_t STAGE   = B_OFF + 64 * LDR;

    const uint32_t aRow = (uint32_t)(lane & 15);
    const uint32_t aCol = (uint32_t)((lane >> 4) & 1) * 16;
    const uint32_t bRow = (uint32_t)((lane & 7) + ((lane >> 4) & 1) * 8);
    const uint32_t bCol = (uint32_t)((lane >> 3) & 1) * 16;

    gemm_stage<TERMS>(Ah, Al, Bx, mBase, nBase, sb, tid, 0, 0);
    CP_COMMIT(); CP_WAIT0(); __syncthreads();

    for (int kc = 0; kc < 4; kc++) {
        if (kc < 3) {
            gemm_stage<TERMS>(Ah, Al, Bx, mBase, nBase, sb, tid, kc + 1, (kc + 1) & 1);
            CP_COMMIT();
        }
        const uint32_t kb = sb + (uint32_t)(kc & 1) * STAGE;
#pragma unroll
        for (int ks = 0; ks < 4; ks++) {
            const uint32_t kOff = (uint32_t)ks * 32;
            uint32_t af[2][4], bf[2][4];
#pragma unroll
            for (int nj = 0; nj < 2; nj++) {
                uint32_t row = (uint32_t)(warpN * 32 + nj * 16) + bRow;
                ldm_x4(bf[nj], kb + B_OFF + row * LDR + kOff + bCol);
            }
#pragma unroll
            for (int mi = 0; mi < 2; mi++) {
                uint32_t row = (uint32_t)(warpM * 32 + mi * 16) + aRow;
                ldm_x4(af[mi], kb + row * LDR + kOff + aCol);
            }
#pragma unroll
            for (int mi = 0; mi < 2; mi++)
#pragma unroll
                for (int nj = 0; nj < 2; nj++) {
                    mma_f16(acc[mi][2 * nj + 0], af[mi], &bf[nj][0]);
                    mma_f16(acc[mi][2 * nj + 1], af[mi], &bf[nj][2]);
                }
            if (TERMS == 2) {
#pragma unroll
                for (int mi = 0; mi < 2; mi++) {
                    uint32_t row = (uint32_t)(warpM * 32 + mi * 16) + aRow;
                    ldm_x4(af[mi], kb + AL_OFF + row * LDR + kOff + aCol);
                }
#pragma unroll
                for (int mi = 0; mi < 2; mi++)
#pragma unroll
                    for (int nj = 0; nj < 2; nj++) {
                        mma_f16(acc[mi][2 * nj + 0], af[mi], &bf[nj][0]);
                        mma_f16(acc[mi][2 * nj + 1], af[mi], &bf[nj][2]);
                    }
            }
        }
        if (kc < 3) { CP_WAIT0(); __syncthreads(); }
    }
}

// ---------------------------------------------------------------------------
// QKV projection: 64m x 64n tiles, grid (16,4,24). Q/K 2-term, V 1-term.
// Q scale includes 1/sqrt(dk) * log2(e).
// ---------------------------------------------------------------------------
__global__ void __launch_bounds__(128, 4) qkv_gemm(
    const float* __restrict__ bq, const float* __restrict__ bk,
    const float* __restrict__ bv)
{
    extern __shared__ char smc[];
    const uint32_t sb = smem_u32(smc);
    const int tid = threadIdx.x, lane = tid & 31, wid = tid >> 5;
    const int z = blockIdx.z, b = z / 3, sel = z - 3 * b;
    const int mBase = blockIdx.y * 64;
    const int nBase = blockIdx.x * 64;
    const int warpM = wid >> 1, warpN = wid & 1;

    const float* bias = sel == 0 ? bq : (sel == 1 ? bk : bv);
    const float scale = sel == 0 ? 0.17677669529663687f * 1.4426950408889634f : 1.0f;
    __half* Yp = sel == 0 ? g_q : (sel == 1 ? g_k : g_v);

    float acc[2][4][4];
#pragma unroll
    for (int i = 0; i < 2; i++)
#pragma unroll
        for (int j = 0; j < 4; j++)
#pragma unroll
            for (int r = 0; r < 4; r++) acc[i][j][r] = 0.f;

    const __half* Xb = g_xt + (size_t)b * 1024 * 256;
    if (sel == 2)
        gemm_run<1>(g_wh + 2 * 65536, nullptr, Xb,
                    mBase, nBase, sb, warpM, warpN, lane, tid, acc);
    else
        gemm_run<2>(g_wh + sel * 65536, g_wl + sel * 65536, Xb,
                    mBase, nBase, sb, warpM, warpN, lane, tid, acc);

    const int g = lane >> 2, t4 = lane & 3;
#pragma unroll
    for (int mi = 0; mi < 2; mi++) {
        int m0 = mBase + warpM * 32 + mi * 16 + g;
        float bi0 = bias[m0], bi1 = bias[m0 + 8];
#pragma unroll
        for (int n8 = 0; n8 < 4; n8++) {
            int n = nBase + warpN * 32 + n8 * 8 + t4 * 2;
#pragma unroll
            for (int half = 0; half < 2; half++) {
                int mm = half ? m0 + 8 : m0;
                float bi = half ? bi1 : bi0;
                float v0 = (acc[mi][n8][2 * half + 0] + bi) * scale;
                float v1 = (acc[mi][n8][2 * half + 1] + bi) * scale;
                size_t base = (((size_t)b * 8 + (mm >> 5)) * 1024 + n) * 32 + (mm & 31);
                Yp[base] = __float2half_rn(v0);
                Yp[base + 32] = __float2half_rn(v1);
            }
        }
    }
}

// ---------------------------------------------------------------------------
// Output projection: 64m x 64n tiles, grid (16,4,8). 2-term. fp32 out [b,c,n].
// ---------------------------------------------------------------------------
__global__ void __launch_bounds__(128, 4) out_gemm(
    const float* __restrict__ bo, float* __restrict__ Y)
{
    extern __shared__ char smc[];
    const uint32_t sb = smem_u32(smc);
    const int tid = threadIdx.x, lane = tid & 31, wid = tid >> 5;
    const int b = blockIdx.z;
    const int mBase = blockIdx.y * 64;
    const int nBase = blockIdx.x * 64;
    const int warpM = wid >> 1, warpN = wid & 1;

    float acc[2][4][4];
#pragma unroll
    for (int i = 0; i < 2; i++)
#pragma unroll
        for (int j = 0; j < 4; j++)
#pragma unroll
            for (int r = 0; r < 4; r++) acc[i][j][r] = 0.f;

    gemm_run<2>(g_wh + 3 * 65536, g_wl + 3 * 65536,
                g_o + (size_t)b * 1024 * 256,
                mBase, nBase, sb, warpM, warpN, lane, tid, acc);

    const int g = lane >> 2, t4 = lane & 3;
#pragma unroll
    for (int mi = 0; mi < 2; mi++) {
        int m0 = mBase + warpM * 32 + mi * 16 + g;
        float bi0 = bo[m0], bi1 = bo[m0 + 8];
#pragma unroll
        for (int n8 = 0; n8 < 4; n8++) {
            int n = nBase + warpN * 32 + n8 * 8 + t4 * 2;
#pragma unroll
            for (int half = 0; half < 2; half++) {
                int mm = half ? m0 + 8 : m0;
                float bi = half ? bi1 : bi0;
                float2 v2;
                v2.x = acc[mi][n8][2 * half + 0] + bi;
                v2.y = acc[mi][n8][2 * half + 1] + bi;
                *(float2*)&Y[((size_t)b * 256 + mm) * 1024 + n] = v2;
            }
        }
    }
}

// ---------------------------------------------------------------------------
// Flash attention, pure fp16 (round-13 proven config): 64 q-rows per CTA
// (16/warp), 64-key tiles, cp.async double-buffered, ones-MMA row sums.
// smem: Q 5KB + 2 stages x 10KB = 25KB -> 4 CTAs/SM.
// ---------------------------------------------------------------------------
#define Q_S 0
#define KV_S 5120
#define KV_STAGE 10240
#define ATT_SMEM 25600

__global__ void __launch_bounds__(128, 4) attn_hmma()
{
    extern __shared__ char smc[];
    const uint32_t sb = smem_u32(smc);
    const int tid = threadIdx.x, lane = tid & 31, warp = tid >> 5;
    const int pair = blockIdx.y;
    const int qBase = blockIdx.x * 64;

    const char* q_g = (const char*)(g_q + ((size_t)pair * 1024 + qBase) * 32);
    const char* k_g = (const char*)(g_k + (size_t)pair * 1024 * 32);
    const char* v_g = (const char*)(g_v + (size_t)pair * 1024 * 32);

    // Q: 64 rows x 64B = 256 chunks
#pragma unroll
    for (int i = 0; i < 2; i++) {
        int c = tid + i * 128;
        int row = c >> 2, part = c & 3;
        cp16(sb + Q_S + (uint32_t)row * 80 + (uint32_t)part * 16, q_g + row * 64 + part * 16);
    }

#define KV_LOAD(t, s)                                                          \
    {                                                                          \
        uint32_t base_ = sb + KV_S + (uint32_t)(s) * KV_STAGE;                 \
        size_t go_ = (size_t)(t) * 64 * 64;                                    \
        _Pragma("unroll")                                                      \
        for (int i_ = 0; i_ < 2; i_++) {                                       \
            int c_ = tid + i_ * 128;                                           \
            int row_ = c_ >> 2, part_ = c_ & 3;                                \
            uint32_t doff_ = (uint32_t)row_ * 80 + (uint32_t)part_ * 16;       \
            size_t so_ = go_ + row_ * 64 + part_ * 16;                         \
            cp16(base_ + 0    + doff_, k_g + so_);                             \
            cp16(base_ + 5120 + doff_, v_g + so_);                             \
        }                                                                      \
    }

    KV_LOAD(0, 0); CP_COMMIT();
    CP_WAIT0(); __syncthreads();

    uint32_t qf[2][4];
    {
        uint32_t r = (uint32_t)(warp * 16 + (lane & 15));
        uint32_t cb = (uint32_t)((lane >> 4) & 1) * 16;
        ldm_x4(qf[0], sb + Q_S + r * 80 + cb);
        ldm_x4(qf[1], sb + Q_S + r * 80 + 32 + cb);
    }

    float o[4][4];
#pragma unroll
    for (int i = 0; i < 4; i++)
#pragma unroll
        for (int r = 0; r < 4; r++) o[i][r] = 0.f;
    float rsum[4] = {0.f, 0.f, 0.f, 0.f};

    const uint32_t onesb[2] = {0x3C003C00u, 0x3C003C00u};
    const uint32_t bRow = (uint32_t)((lane & 7) + ((lane >> 4) & 1) * 8);
    const uint32_t bColK = (uint32_t)((lane >> 3) & 1) * 16;
    const uint32_t vRow = (uint32_t)((lane & 7) + ((lane >> 3) & 1) * 8);
    const uint32_t vColB = (uint32_t)((lane >> 4) & 1) * 16;

    for (int t = 0; t < 16; t++) {
        if (t < 15) { KV_LOAD(t + 1, (t + 1) & 1); CP_COMMIT(); }
        const uint32_t kb = sb + KV_S + (uint32_t)(t & 1) * KV_STAGE;

        float s[8][4];
#pragma unroll
        for (int j = 0; j < 8; j++)
#pragma unroll
            for (int r = 0; r < 4; r++) s[j][r] = 0.f;

        // ---- S = Q K^T ----
#pragma unroll
        for (int kg = 0; kg < 4; kg++) {
            uint32_t base = ((uint32_t)(kg * 16) + bRow) * 80 + bColK;
            uint32_t k0f[4], k1f[4];
            ldm_x4(k0f, kb + base);
            ldm_x4(k1f, kb + base + 32);
#pragma unroll
            for (int gs = 0; gs < 2; gs++) {
                float* sj = s[2 * kg + gs];
                mma_f16(sj, qf[0], &k0f[2 * gs]);
                mma_f16(sj, qf[1], &k1f[2 * gs]);
            }
        }

        // ---- O += P V; row sums via ones-MMA ----
#pragma unroll
        for (int kc = 0; kc < 4; kc++) {
            uint32_t vbase = ((uint32_t)(kc * 16) + vRow) * 80 + vColB;
            uint32_t v0f[4], v1f[4];
            ldm_x4t(v0f, kb + 5120 + vbase);
            ldm_x4t(v1f, kb + 5120 + vbase + 32);
            uint32_t ph[4];
            ph[0] = ex2_h2(pack_h2(s[2 * kc][0],     s[2 * kc][1]));
            ph[1] = ex2_h2(pack_h2(s[2 * kc][2],     s[2 * kc][3]));
            ph[2] = ex2_h2(pack_h2(s[2 * kc + 1][0], s[2 * kc + 1][1]));
            ph[3] = ex2_h2(pack_h2(s[2 * kc + 1][2], s[2 * kc + 1][3]));
            mma_f16(o[0], ph, &v0f[0]); mma_f16(o[1], ph, &v0f[2]);
            mma_f16(o[2], ph, &v1f[0]); mma_f16(o[3], ph, &v1f[2]);
            mma_f16(rsum, ph, onesb);
        }
        if (t < 15) { CP_WAIT0(); __syncthreads(); }
    }
#undef KV_LOAD

    // ---- normalize + store fp16 O [b,n,cv]; rsum[0]=row r0, rsum[2]=row r1 ----
    const int g = lane >> 2, t4 = lane & 3;
    const int bb = pair >> 3, hh = pair & 7;
    uint32_t* op = (uint32_t*)g_o;
    const float inv0 = 1.0f / rsum[0], inv1 = 1.0f / rsum[2];
    const size_t r0g = qBase + warp * 16 + g;
    const size_t r1g = r0g + 8;
#pragma unroll
    for (int nt = 0; nt < 4; nt++) {
        int d = nt * 8 + t4 * 2;
        size_t i0 = (((size_t)bb * 1024 + r0g) * 256 + hh * 32 + d) >> 1;
        size_t i1 = (((size_t)bb * 1024 + r1g) * 256 + hh * 32 + d) >> 1;
        op[i0] = pack_h2(o[nt][0] * inv0, o[nt][1] * inv0);
        op[i1] = pack_h2(o[nt][2] * inv1, o[nt][3] * inv1);
    }
}

// ---------------------------------------------------------------------------
extern "C" void kernel_launch(void* const* d_in, const int* in_sizes, int n_in,
                              void* d_out, int out_size)
{
    const float* x  = (const float*)d_in[0];
    const float* Wq = (const float*)d_in[1];
    const float* bq = (const float*)d_in[2];
    const float* Wk = (const float*)d_in[3];
    const float* bk = (const float*)d_in[4];
    const float* Wv = (const float*)d_in[5];
    const float* bv = (const float*)d_in[6];
    const float* Wo = (const float*)d_in[7];
    const float* bo = (const float*)d_in[8];
    float* out = (float*)d_out;

    cudaFuncSetAttribute(qkv_gemm, cudaFuncAttributeMaxDynamicSharedMemorySize, GEMM_SMEM);
    cudaFuncSetAttribute(out_gemm, cudaFuncAttributeMaxDynamicSharedMemorySize, GEMM_SMEM);
    cudaFuncSetAttribute(attn_hmma, cudaFuncAttributeMaxDynamicSharedMemorySize, ATT_SMEM);

    prep_all<<<3072, 256>>>(x, Wq, Wk, Wv, Wo);
    qkv_gemm<<<dim3(16, 4, 24), 128, GEMM_SMEM>>>(bq, bk, bv);
    attn_hmma<<<dim3(16, 64), 128, ATT_SMEM>>>();
    out_gemm<<<dim3(16, 4, 8), 128, GEMM_SMEM>>>(bo, out);
}

// round 17
// speedup vs baseline: 1.1738x; 1.1490x over previous
#include <cuda_runtime.h>
#include <cuda_fp16.h>
#include <cstdint>

// Problem: B=8, C=256, H=W=32 -> N=1024, heads=8, dk=dv=32.

// ---------------- helpers ----------------
__device__ __forceinline__ uint32_t smem_u32(const void* p) {
    uint32_t a;
    asm("{ .reg .u64 t; cvta.to.shared.u64 t, %1; cvt.u32.u64 %0, t; }" : "=r"(a) : "l"(p));
    return a;
}
__device__ __forceinline__ void ldm_x4(uint32_t r[4], uint32_t addr) {
    asm volatile("ldmatrix.sync.aligned.m8n8.x4.shared.b16 {%0,%1,%2,%3}, [%4];"
                 : "=r"(r[0]), "=r"(r[1]), "=r"(r[2]), "=r"(r[3]) : "r"(addr));
}
__device__ __forceinline__ void ldm_x4t(uint32_t r[4], uint32_t addr) {
    asm volatile("ldmatrix.sync.aligned.m8n8.x4.trans.shared.b16 {%0,%1,%2,%3}, [%4];"
                 : "=r"(r[0]), "=r"(r[1]), "=r"(r[2]), "=r"(r[3]) : "r"(addr));
}
__device__ __forceinline__ void mma_f16(float* c, const uint32_t* a, const uint32_t* b) {
    asm volatile(
        "mma.sync.aligned.m16n8k16.row.col.f32.f16.f16.f32 "
        "{%0,%1,%2,%3}, {%4,%5,%6,%7}, {%8,%9}, {%0,%1,%2,%3};"
        : "+f"(c[0]), "+f"(c[1]), "+f"(c[2]), "+f"(c[3])
        : "r"(a[0]), "r"(a[1]), "r"(a[2]), "r"(a[3]), "r"(b[0]), "r"(b[1]));
}
__device__ __forceinline__ uint32_t pack_h2(float x, float y) {
    __half2 p = __float22half2_rn(make_float2(x, y));
    return *(uint32_t*)&p;
}
__device__ __forceinline__ uint32_t ex2_h2(uint32_t x) {
    uint32_t y; asm("ex2.approx.f16x2 %0, %1;" : "=r"(y) : "r"(x)); return y;
}
__device__ __forceinline__ void cp16(uint32_t dst, const void* src) {
    asm volatile("cp.async.cg.shared.global [%0], [%1], 16;" :: "r"(dst), "l"(src));
}
#define CP_COMMIT() asm volatile("cp.async.commit_group;" ::: "memory")
#define CP_WAIT0()  asm volatile("cp.async.wait_group 0;" ::: "memory")

// ---------------- scratch (all pure fp16) ----------------
__device__ __half g_wh[4 * 65536];       // Wq,Wk,Wv,Wo [m][k]
__device__ __half g_xt[8*1024*256];      // [b, n, c]
__device__ __half g_q [8*8*1024*32];     // [b,h,n,d] (scaled)
__device__ __half g_k [8*8*1024*32];     // [b,h,n,d]
__device__ __half g_v [8*8*1024*32];     // [b,h,n,d]
__device__ __half g_o [8*1024*256];      // [b,n,cv]

// ---------------------------------------------------------------------------
// Fused prep: blocks 0..2047 transpose x -> xT fp16; 2048..3071 round weights.
// ---------------------------------------------------------------------------
__global__ void __launch_bounds__(256) prep_all(
    const float* __restrict__ x,
    const float* __restrict__ Wq, const float* __restrict__ Wk,
    const float* __restrict__ Wv, const float* __restrict__ Wo)
{
    __shared__ float tile[32][33];
    const int blk = blockIdx.x;
    const int tid = threadIdx.x;
    if (blk < 2048) {
        const int nblk = blk & 31, cblk = (blk >> 5) & 7, b = blk >> 8;
        const int n0 = nblk * 32, c0 = cblk * 32;
        const int tx = tid & 31, ty = tid >> 5;
#pragma unroll
        for (int i = 0; i < 4; i++)
            tile[ty + 8 * i][tx] = x[((size_t)b * 256 + c0 + ty + 8 * i) * 1024 + n0 + tx];
        __syncthreads();
#pragma unroll
        for (int i = 0; i < 4; i++)
            g_xt[((size_t)b * 1024 + n0 + ty + 8 * i) * 256 + c0 + tx] =
                __float2half_rn(tile[tx][ty + 8 * i]);
    } else {
        int idx = (blk - 2048) * 256 + tid;     // 0..262143
        int sel = idx >> 16, off = idx & 65535;
        const float* W = sel == 0 ? Wq : (sel == 1 ? Wk : (sel == 2 ? Wv : Wo));
        g_wh[idx] = __float2half_rn(W[off]);
    }
}

// ---------------------------------------------------------------------------
// GEMM core: acc += W[64m x 256k] * X[64n x 256k]^T, pure fp16 (1 term).
// 128-thread CTA, 4 warps as 2m x 2n (warp tile 32m x 32n).
// K-chunks of 64 (pitch-144, conflict-free ldmatrix), double-buffered,
// 4 barrier rounds. smem 2 x 18.4KB = 36.9KB -> 4 CTAs/SM.
// ---------------------------------------------------------------------------
#define LDR 144
#define GEMM_SMEM 36864

__device__ __forceinline__ void gemm_stage(
    const __half* __restrict__ Ah, const __half* __restrict__ Bx,
    int mBase, int nBase, uint32_t sb, int tid, int kc, int s)
{
    constexpr uint32_t A_BYTES = 64u * LDR;
    constexpr uint32_t B_OFF   = A_BYTES;
    constexpr uint32_t STAGE   = B_OFF + 64 * LDR;

    uint32_t base = sb + (uint32_t)s * STAGE;
#pragma unroll
    for (int i = 0; i < 8; i++) {             // 128 rows x 8 chunks / 128 thr
        int idx = tid + i * 128;
        int r = idx >> 3, part = idx & 7;
        uint32_t cOff = (uint32_t)part * 16;
        if (r < 64) {
            cp16(base + (uint32_t)r * LDR + cOff,
                 Ah + (size_t)(mBase + r) * 256 + kc * 64 + part * 8);
        } else {
            int rr = r - 64;
            cp16(base + B_OFF + (uint32_t)rr * LDR + cOff,
                 Bx + (size_t)(nBase + rr) * 256 + kc * 64 + part * 8);
        }
    }
}

__device__ __forceinline__ void gemm_run(
    const __half* __restrict__ Ah, const __half* __restrict__ Bx,
    int mBase, int nBase, uint32_t sb,
    int warpM, int warpN, int lane, int tid, float acc[2][4][4])
{
    constexpr uint32_t A_BYTES = 64u * LDR;
    constexpr uint32_t B_OFF   = A_BYTES;
    constexpr uint32_t STAGE   = B_OFF + 64 * LDR;

    const uint32_t aRow = (uint32_t)(lane & 15);
    const uint32_t aCol = (uint32_t)((lane >> 4) & 1) * 16;
    const uint32_t bRow = (uint32_t)((lane & 7) + ((lane >> 4) & 1) * 8);
    const uint32_t bCol = (uint32_t)((lane >> 3) & 1) * 16;

    gemm_stage(Ah, Bx, mBase, nBase, sb, tid, 0, 0);
    CP_COMMIT(); CP_WAIT0(); __syncthreads();

    for (int kc = 0; kc < 4; kc++) {
        if (kc < 3) {
            gemm_stage(Ah, Bx, mBase, nBase, sb, tid, kc + 1, (kc + 1) & 1);
            CP_COMMIT();
        }
        const uint32_t kb = sb + (uint32_t)(kc & 1) * STAGE;
#pragma unroll
        for (int ks = 0; ks < 4; ks++) {
            const uint32_t kOff = (uint32_t)ks * 32;
            uint32_t af[2][4], bf[2][4];
#pragma unroll
            for (int nj = 0; nj < 2; nj++) {
                uint32_t row = (uint32_t)(warpN * 32 + nj * 16) + bRow;
                ldm_x4(bf[nj], kb + B_OFF + row * LDR + kOff + bCol);
            }
#pragma unroll
            for (int mi = 0; mi < 2; mi++) {
                uint32_t row = (uint32_t)(warpM * 32 + mi * 16) + aRow;
                ldm_x4(af[mi], kb + row * LDR + kOff + aCol);
            }
#pragma unroll
            for (int mi = 0; mi < 2; mi++)
#pragma unroll
                for (int nj = 0; nj < 2; nj++) {
                    mma_f16(acc[mi][2 * nj + 0], af[mi], &bf[nj][0]);
                    mma_f16(acc[mi][2 * nj + 1], af[mi], &bf[nj][2]);
                }
        }
        if (kc < 3) { CP_WAIT0(); __syncthreads(); }
    }
}

// ---------------------------------------------------------------------------
// QKV projection: 64m x 64n tiles, grid (16,4,24). Pure fp16 weights.
// Q scale includes 1/sqrt(dk) * log2(e).
// ---------------------------------------------------------------------------
__global__ void __launch_bounds__(128, 4) qkv_gemm(
    const float* __restrict__ bq, const float* __restrict__ bk,
    const float* __restrict__ bv)
{
    extern __shared__ char smc[];
    const uint32_t sb = smem_u32(smc);
    const int tid = threadIdx.x, lane = tid & 31, wid = tid >> 5;
    const int z = blockIdx.z, b = z / 3, sel = z - 3 * b;
    const int mBase = blockIdx.y * 64;
    const int nBase = blockIdx.x * 64;
    const int warpM = wid >> 1, warpN = wid & 1;

    const float* bias = sel == 0 ? bq : (sel == 1 ? bk : bv);
    const float scale = sel == 0 ? 0.17677669529663687f * 1.4426950408889634f : 1.0f;
    __half* Yp = sel == 0 ? g_q : (sel == 1 ? g_k : g_v);

    float acc[2][4][4];
#pragma unroll
    for (int i = 0; i < 2; i++)
#pragma unroll
        for (int j = 0; j < 4; j++)
#pragma unroll
            for (int r = 0; r < 4; r++) acc[i][j][r] = 0.f;

    gemm_run(g_wh + sel * 65536, g_xt + (size_t)b * 1024 * 256,
             mBase, nBase, sb, warpM, warpN, lane, tid, acc);

    const int g = lane >> 2, t4 = lane & 3;
#pragma unroll
    for (int mi = 0; mi < 2; mi++) {
        int m0 = mBase + warpM * 32 + mi * 16 + g;
        float bi0 = bias[m0], bi1 = bias[m0 + 8];
#pragma unroll
        for (int n8 = 0; n8 < 4; n8++) {
            int n = nBase + warpN * 32 + n8 * 8 + t4 * 2;
#pragma unroll
            for (int half = 0; half < 2; half++) {
                int mm = half ? m0 + 8 : m0;
                float bi = half ? bi1 : bi0;
                float v0 = (acc[mi][n8][2 * half + 0] + bi) * scale;
                float v1 = (acc[mi][n8][2 * half + 1] + bi) * scale;
                size_t base = (((size_t)b * 8 + (mm >> 5)) * 1024 + n) * 32 + (mm & 31);
                Yp[base] = __float2half_rn(v0);
                Yp[base + 32] = __float2half_rn(v1);
            }
        }
    }
}

// ---------------------------------------------------------------------------
// Output projection: 64m x 64n tiles, grid (16,4,8). Pure fp16 Wo.
// fp32 out [b,c,n].
// ---------------------------------------------------------------------------
__global__ void __launch_bounds__(128, 4) out_gemm(
    const float* __restrict__ bo, float* __restrict__ Y)
{
    extern __shared__ char smc[];
    const uint32_t sb = smem_u32(smc);
    const int tid = threadIdx.x, lane = tid & 31, wid = tid >> 5;
    const int b = blockIdx.z;
    const int mBase = blockIdx.y * 64;
    const int nBase = blockIdx.x * 64;
    const int warpM = wid >> 1, warpN = wid & 1;

    float acc[2][4][4];
#pragma unroll
    for (int i = 0; i < 2; i++)
#pragma unroll
        for (int j = 0; j < 4; j++)
#pragma unroll
            for (int r = 0; r < 4; r++) acc[i][j][r] = 0.f;

    gemm_run(g_wh + 3 * 65536, g_o + (size_t)b * 1024 * 256,
             mBase, nBase, sb, warpM, warpN, lane, tid, acc);

    const int g = lane >> 2, t4 = lane & 3;
#pragma unroll
    for (int mi = 0; mi < 2; mi++) {
        int m0 = mBase + warpM * 32 + mi * 16 + g;
        float bi0 = bo[m0], bi1 = bo[m0 + 8];
#pragma unroll
        for (int n8 = 0; n8 < 4; n8++) {
            int n = nBase + warpN * 32 + n8 * 8 + t4 * 2;
#pragma unroll
            for (int half = 0; half < 2; half++) {
                int mm = half ? m0 + 8 : m0;
                float bi = half ? bi1 : bi0;
                float2 v2;
                v2.x = acc[mi][n8][2 * half + 0] + bi;
                v2.y = acc[mi][n8][2 * half + 1] + bi;
                *(float2*)&Y[((size_t)b * 256 + mm) * 1024 + n] = v2;
            }
        }
    }
}

// ---------------------------------------------------------------------------
// Flash attention, pure fp16 (round-13 proven config): 64 q-rows per CTA
// (16/warp), 64-key tiles, cp.async double-buffered, ones-MMA row sums.
// smem: Q 5KB + 2 stages x 10KB = 25KB -> 4 CTAs/SM.
// ---------------------------------------------------------------------------
#define Q_S 0
#define KV_S 5120
#define KV_STAGE 10240
#define ATT_SMEM 25600

__global__ void __launch_bounds__(128, 4) attn_hmma()
{
    extern __shared__ char smc[];
    const uint32_t sb = smem_u32(smc);
    const int tid = threadIdx.x, lane = tid & 31, warp = tid >> 5;
    const int pair = blockIdx.y;
    const int qBase = blockIdx.x * 64;

    const char* q_g = (const char*)(g_q + ((size_t)pair * 1024 + qBase) * 32);
    const char* k_g = (const char*)(g_k + (size_t)pair * 1024 * 32);
    const char* v_g = (const char*)(g_v + (size_t)pair * 1024 * 32);

    // Q: 64 rows x 64B = 256 chunks
#pragma unroll
    for (int i = 0; i < 2; i++) {
        int c = tid + i * 128;
        int row = c >> 2, part = c & 3;
        cp16(sb + Q_S + (uint32_t)row * 80 + (uint32_t)part * 16, q_g + row * 64 + part * 16);
    }

#define KV_LOAD(t, s)                                                          \
    {                                                                          \
        uint32_t base_ = sb + KV_S + (uint32_t)(s) * KV_STAGE;                 \
        size_t go_ = (size_t)(t) * 64 * 64;                                    \
        _Pragma("unroll")                                                      \
        for (int i_ = 0; i_ < 2; i_++) {                                       \
            int c_ = tid + i_ * 128;                                           \
            int row_ = c_ >> 2, part_ = c_ & 3;                                \
            uint32_t doff_ = (uint32_t)row_ * 80 + (uint32_t)part_ * 16;       \
            size_t so_ = go_ + row_ * 64 + part_ * 16;                         \
            cp16(base_ + 0    + doff_, k_g + so_);                             \
            cp16(base_ + 5120 + doff_, v_g + so_);                             \
        }                                                                      \
    }

    KV_LOAD(0, 0); CP_COMMIT();
    CP_WAIT0(); __syncthreads();

    uint32_t qf[2][4];
    {
        uint32_t r = (uint32_t)(warp * 16 + (lane & 15));
        uint32_t cb = (uint32_t)((lane >> 4) & 1) * 16;
        ldm_x4(qf[0], sb + Q_S + r * 80 + cb);
        ldm_x4(qf[1], sb + Q_S + r * 80 + 32 + cb);
    }

    float o[4][4];
#pragma unroll
    for (int i = 0; i < 4; i++)
#pragma unroll
        for (int r = 0; r < 4; r++) o[i][r] = 0.f;
    float rsum[4] = {0.f, 0.f, 0.f, 0.f};

    const uint32_t onesb[2] = {0x3C003C00u, 0x3C003C00u};
    const uint32_t bRow = (uint32_t)((lane & 7) + ((lane >> 4) & 1) * 8);
    const uint32_t bColK = (uint32_t)((lane >> 3) & 1) * 16;
    const uint32_t vRow = (uint32_t)((lane & 7) + ((lane >> 3) & 1) * 8);
    const uint32_t vColB = (uint32_t)((lane >> 4) & 1) * 16;

    for (int t = 0; t < 16; t++) {
        if (t < 15) { KV_LOAD(t + 1, (t + 1) & 1); CP_COMMIT(); }
        const uint32_t kb = sb + KV_S + (uint32_t)(t & 1) * KV_STAGE;

        float s[8][4];
#pragma unroll
        for (int j = 0; j < 8; j++)
#pragma unroll
            for (int r = 0; r < 4; r++) s[j][r] = 0.f;

        // ---- S = Q K^T ----
#pragma unroll
        for (int kg = 0; kg < 4; kg++) {
            uint32_t base = ((uint32_t)(kg * 16) + bRow) * 80 + bColK;
            uint32_t k0f[4], k1f[4];
            ldm_x4(k0f, kb + base);
            ldm_x4(k1f, kb + base + 32);
#pragma unroll
            for (int gs = 0; gs < 2; gs++) {
                float* sj = s[2 * kg + gs];
                mma_f16(sj, qf[0], &k0f[2 * gs]);
                mma_f16(sj, qf[1], &k1f[2 * gs]);
            }
        }

        // ---- O += P V; row sums via ones-MMA ----
#pragma unroll
        for (int kc = 0; kc < 4; kc++) {
            uint32_t vbase = ((uint32_t)(kc * 16) + vRow) * 80 + vColB;
            uint32_t v0f[4], v1f[4];
            ldm_x4t(v0f, kb + 5120 + vbase);
            ldm_x4t(v1f, kb + 5120 + vbase + 32);
            uint32_t ph[4];
            ph[0] = ex2_h2(pack_h2(s[2 * kc][0],     s[2 * kc][1]));
            ph[1] = ex2_h2(pack_h2(s[2 * kc][2],     s[2 * kc][3]));
            ph[2] = ex2_h2(pack_h2(s[2 * kc + 1][0], s[2 * kc + 1][1]));
            ph[3] = ex2_h2(pack_h2(s[2 * kc + 1][2], s[2 * kc + 1][3]));
            mma_f16(o[0], ph, &v0f[0]); mma_f16(o[1], ph, &v0f[2]);
            mma_f16(o[2], ph, &v1f[0]); mma_f16(o[3], ph, &v1f[2]);
            mma_f16(rsum, ph, onesb);
        }
        if (t < 15) { CP_WAIT0(); __syncthreads(); }
    }
#undef KV_LOAD

    // ---- normalize + store fp16 O [b,n,cv]; rsum[0]=row r0, rsum[2]=row r1 ----
    const int g = lane >> 2, t4 = lane & 3;
    const int bb = pair >> 3, hh = pair & 7;
    uint32_t* op = (uint32_t*)g_o;
    const float inv0 = 1.0f / rsum[0], inv1 = 1.0f / rsum[2];
    const size_t r0g = qBase + warp * 16 + g;
    const size_t r1g = r0g + 8;
#pragma unroll
    for (int nt = 0; nt < 4; nt++) {
        int d = nt * 8 + t4 * 2;
        size_t i0 = (((size_t)bb * 1024 + r0g) * 256 + hh * 32 + d) >> 1;
        size_t i1 = (((size_t)bb * 1024 + r1g) * 256 + hh * 32 + d) >> 1;
        op[i0] = pack_h2(o[nt][0] * inv0, o[nt][1] * inv0);
        op[i1] = pack_h2(o[nt][2] * inv1, o[nt][3] * inv1);
    }
}

// ---------------------------------------------------------------------------
extern "C" void kernel_launch(void* const* d_in, const int* in_sizes, int n_in,
                              void* d_out, int out_size)
{
    const float* x  = (const float*)d_in[0];
    const float* Wq = (const float*)d_in[1];
    const float* bq = (const float*)d_in[2];
    const float* Wk = (const float*)d_in[3];
    const float* bk = (const float*)d_in[4];
    const float* Wv = (const float*)d_in[5];
    const float* bv = (const float*)d_in[6];
    const float* Wo = (const float*)d_in[7];
    const float* bo = (const float*)d_in[8];
    float* out = (float*)d_out;

    cudaFuncSetAttribute(qkv_gemm, cudaFuncAttributeMaxDynamicSharedMemorySize, GEMM_SMEM);
    cudaFuncSetAttribute(out_gemm, cudaFuncAttributeMaxDynamicSharedMemorySize, GEMM_SMEM);
    cudaFuncSetAttribute(attn_hmma, cudaFuncAttributeMaxDynamicSharedMemorySize, ATT_SMEM);

    prep_all<<<3072, 256>>>(x, Wq, Wk, Wv, Wo);
    qkv_gemm<<<dim3(16, 4, 24), 128, GEMM_SMEM>>>(bq, bk, bv);
    attn_hmma<<<dim3(16, 64), 128, ATT_SMEM>>>();
    out_gemm<<<dim3(16, 4, 8), 128, GEMM_SMEM>>>(bo, out);
}